// round 3
// baseline (speedup 1.0000x reference)
#include <cuda_runtime.h>
#include <cuda_fp16.h>
#include <stdint.h>

// ---------------------------------------------------------------------------
// Static device scratch (allocation-free rule): fp16 copies of x and dequant W
// ---------------------------------------------------------------------------
static __device__ __half g_x16[33554432];   // 8192 * 4096
static __device__ __half g_w16[67108864];   // 16384 * 4096

#define BM 128
#define BN 128
#define BK 64
#define STAGES 4
#define A_BYTES 16384            // 128 rows * 64 halves * 2B  (row = 128B)
#define STAGE_BYTES 32768        // A + B

// ---------------------------------------------------------------------------
// PTX helpers (plain sm_90-safe instructions only — harness targets sm_103
// without the 'a' feature suffix, so tcgen05/TMA-arch ops won't assemble)
// ---------------------------------------------------------------------------
__device__ __forceinline__ uint32_t cvta_shared(const void* p) {
    uint32_t a;
    asm("{ .reg .u64 t; cvta.to.shared.u64 t, %1; cvt.u32.u64 %0, t; }"
        : "=r"(a) : "l"(p));
    return a;
}
__device__ __forceinline__ void cp_async16(uint32_t dst, const void* src) {
    asm volatile("cp.async.cg.shared.global [%0], [%1], 16;"
                 :: "r"(dst), "l"(src));
}
__device__ __forceinline__ void cp_commit() {
    asm volatile("cp.async.commit_group;" ::: "memory");
}
__device__ __forceinline__ void cp_wait2() {
    asm volatile("cp.async.wait_group 2;" ::: "memory");
}
__device__ __forceinline__ void ldsm_x4(uint32_t* r, uint32_t addr) {
    asm volatile("ldmatrix.sync.aligned.m8n8.x4.shared.b16 {%0,%1,%2,%3}, [%4];"
                 : "=r"(r[0]), "=r"(r[1]), "=r"(r[2]), "=r"(r[3]) : "r"(addr));
}
__device__ __forceinline__ void mma16816(float* c, const uint32_t* a, const uint32_t* b) {
    asm volatile(
        "mma.sync.aligned.m16n8k16.row.col.f32.f16.f16.f32 "
        "{%0,%1,%2,%3}, {%4,%5,%6,%7}, {%8,%9}, {%0,%1,%2,%3};"
        : "+f"(c[0]), "+f"(c[1]), "+f"(c[2]), "+f"(c[3])
        : "r"(a[0]), "r"(a[1]), "r"(a[2]), "r"(a[3]), "r"(b[0]), "r"(b[1]));
}

// ---------------------------------------------------------------------------
// Conversion kernels
// ---------------------------------------------------------------------------
__global__ void convert_x_kernel(const float4* __restrict__ x, long long n4) {
    uint2* o = reinterpret_cast<uint2*>(g_x16);
    long long stride = (long long)gridDim.x * blockDim.x;
    for (long long i = (long long)blockIdx.x * blockDim.x + threadIdx.x; i < n4; i += stride) {
        float4 v = x[i];
        __half2 h0 = __floats2half2_rn(v.x, v.y);
        __half2 h1 = __floats2half2_rn(v.z, v.w);
        uint2 u;
        u.x = *reinterpret_cast<uint32_t*>(&h0);
        u.y = *reinterpret_cast<uint32_t*>(&h1);
        o[i] = u;
    }
}

// W dequant: w16[n,k] = fp16( w[n,k] * scale_inv[n/128, k/128] )
__global__ void convert_w_kernel(const float4* __restrict__ w, const float* __restrict__ sc,
                                 int K, int N) {
    int K4 = K >> 2;
    int KB = K >> 7;
    int k4 = blockIdx.x * blockDim.x + threadIdx.x;
    int n  = blockIdx.y;
    if (k4 >= K4) return;
    long long i = (long long)n * K4 + k4;
    float s = __ldg(sc + (n >> 7) * KB + (k4 >> 5));
    float4 v = w[i];
    __half2 h0 = __floats2half2_rn(v.x * s, v.y * s);
    __half2 h1 = __floats2half2_rn(v.z * s, v.w * s);
    uint2 u;
    u.x = *reinterpret_cast<uint32_t*>(&h0);
    u.y = *reinterpret_cast<uint32_t*>(&h1);
    reinterpret_cast<uint2*>(g_w16)[i] = u;
}

// ---------------------------------------------------------------------------
// HMMA GEMM: out[m,n] = sum_k x16[m,k] * w16[n,k] + bias[n]
// 128x128 tile/CTA, BK=64, 4-stage cp.async pipeline, 8 warps (4x2),
// warp tile 32x64, mma.sync.m16n8k16, fp32 accum in registers.
// ---------------------------------------------------------------------------
__global__ void __launch_bounds__(256, 1)
gemm_f16_kernel(const float* __restrict__ bias, float* __restrict__ out,
                int M, int N, int K, int NT) {
    extern __shared__ char smem[];
    const uint32_t sbase = cvta_shared(smem);
    const int tid  = threadIdx.x;
    const int warp = tid >> 5;
    const int lane = tid & 31;

    // Grouped raster: groups of 8 M-tiles -> per-wave L2 working set small
    int bid = blockIdx.x;
    int tg  = NT << 3;
    int gq  = bid / tg;
    int rem = bid % tg;
    int mt  = (gq << 3) + (rem & 7);
    int nt  = rem >> 3;

    const __half* Ag = g_x16 + (size_t)mt * BM * K;
    const __half* Bg = g_w16 + (size_t)nt * BN * K;
    const int NKT = K / BK;

    // ---- cp.async per-thread offsets (1024 16B chunks per 16KB half) ----
    uint32_t sofs[4];
    size_t   gofs[4];
#pragma unroll
    for (int i = 0; i < 4; i++) {
        int chunk = tid + (i << 8);      // 0..1023
        int row   = chunk >> 3;          // 0..127
        int cc    = chunk & 7;           // 16B column chunk
        uint32_t so = (uint32_t)(row * 128 + cc * 16);
        sofs[i] = so ^ ((so >> 3) & 0x70);          // SW128 swizzle
        gofs[i] = (size_t)row * K + cc * 8;         // elements
    }
    auto load_stage = [&](int s) {
        uint32_t sb = sbase + (uint32_t)(s & (STAGES - 1)) * STAGE_BYTES;
        const __half* ga = Ag + s * BK;
        const __half* gb = Bg + s * BK;
#pragma unroll
        for (int i = 0; i < 4; i++) {
            cp_async16(sb + sofs[i],           ga + gofs[i]);
            cp_async16(sb + A_BYTES + sofs[i], gb + gofs[i]);
        }
    };

    for (int s = 0; s < STAGES - 1; s++) { load_stage(s); cp_commit(); }

    // ---- per-lane ldmatrix address components ----
    const int wm = warp & 3;             // 0..3 -> M offset wm*32
    const int wn = warp >> 2;            // 0..1 -> N offset wn*64
    // A: 2 m16 frags
    uint32_t aoff[2], acx[2];
    const uint32_t ahi = (uint32_t)((lane >> 4) << 4);
#pragma unroll
    for (int mi = 0; mi < 2; mi++) {
        int row = wm * 32 + mi * 16 + (lane & 15);
        aoff[mi] = (uint32_t)(row * 128);
        acx[mi]  = (uint32_t)((row & 7) << 4);
    }
    // B: 4 n16 frag-pairs
    uint32_t boff[4], bcx[4];
    const uint32_t bhi = (uint32_t)(((lane >> 3) & 1) << 4);
#pragma unroll
    for (int bp = 0; bp < 4; bp++) {
        int row = wn * 64 + bp * 16 + (lane & 7) + ((lane >> 4) << 3);
        boff[bp] = (uint32_t)(row * 128);
        bcx[bp]  = (uint32_t)((row & 7) << 4);
    }

    float c[2][8][4];
#pragma unroll
    for (int mi = 0; mi < 2; mi++)
#pragma unroll
        for (int f = 0; f < 8; f++)
#pragma unroll
            for (int r = 0; r < 4; r++) c[mi][f][r] = 0.0f;

    for (int kt = 0; kt < NKT; ++kt) {
        cp_wait2();                 // stage kt landed
        __syncthreads();

        int sp = kt + STAGES - 1;   // issue next loads first, then compute
        if (sp < NKT) load_stage(sp);
        cp_commit();                // commit (possibly empty) to keep counts

        uint32_t sA = sbase + (uint32_t)(kt & (STAGES - 1)) * STAGE_BYTES;
        uint32_t sB = sA + A_BYTES;
#pragma unroll
        for (int ks = 0; ks < 4; ks++) {
            uint32_t a[2][4], b[4][4];
#pragma unroll
            for (int mi = 0; mi < 2; mi++)
                ldsm_x4(a[mi], sA + aoff[mi] + ((ks * 32 + ahi) ^ acx[mi]));
#pragma unroll
            for (int bp = 0; bp < 4; bp++)
                ldsm_x4(b[bp], sB + boff[bp] + ((ks * 32 + bhi) ^ bcx[bp]));
#pragma unroll
            for (int mi = 0; mi < 2; mi++)
#pragma unroll
                for (int bp = 0; bp < 4; bp++) {
                    mma16816(c[mi][2 * bp + 0], a[mi], b[bp] + 0);
                    mma16816(c[mi][2 * bp + 1], a[mi], b[bp] + 2);
                }
        }
    }

    // ---- epilogue: add bias, store float2 pairs ----
    const int mbase = mt * BM + wm * 32 + (lane >> 2);
    const int nbase = nt * BN + wn * 64 + (lane & 3) * 2;
#pragma unroll
    for (int mi = 0; mi < 2; mi++) {
#pragma unroll
        for (int f = 0; f < 8; f++) {
            int n0 = nbase + f * 8;
            float b0 = __ldg(bias + n0);
            float b1 = __ldg(bias + n0 + 1);
            int m0 = mbase + mi * 16;
            float2 v0 = make_float2(c[mi][f][0] + b0, c[mi][f][1] + b1);
            float2 v1 = make_float2(c[mi][f][2] + b0, c[mi][f][3] + b1);
            *reinterpret_cast<float2*>(out + (size_t)m0 * N + n0)       = v0;
            *reinterpret_cast<float2*>(out + (size_t)(m0 + 8) * N + n0) = v1;
        }
    }
}

// ---------------------------------------------------------------------------
// Launch
// ---------------------------------------------------------------------------
extern "C" void kernel_launch(void* const* d_in, const int* in_sizes, int n_in,
                              void* d_out, int out_size) {
    const float* x    = (const float*)d_in[0];
    const float* w    = (const float*)d_in[1];
    const float* sc   = (const float*)d_in[2];
    const float* bias = (const float*)d_in[3];
    float* out = (float*)d_out;

    int N = in_sizes[3];
    int K = in_sizes[1] / N;
    int M = in_sizes[0] / K;

    convert_x_kernel<<<8192, 256>>>((const float4*)x, (long long)M * K / 4);

    dim3 gw((K / 4 + 255) / 256, N);
    convert_w_kernel<<<gw, 256>>>((const float4*)w, sc, K, N);

    int MT = M / BM, NT = N / BN;
    size_t smem_bytes = (size_t)STAGES * STAGE_BYTES;
    cudaFuncSetAttribute(gemm_f16_kernel,
                         cudaFuncAttributeMaxDynamicSharedMemorySize, (int)smem_bytes);
    gemm_f16_kernel<<<MT * NT, 256, smem_bytes>>>(bias, out, M, N, K, NT);
}

// round 7
// speedup vs baseline: 1.1706x; 1.1706x over previous
#include <cuda_runtime.h>
#include <cuda_fp16.h>
#include <stdint.h>

// ---------------------------------------------------------------------------
// Static device scratch (allocation-free rule): fp16 copies of x and dequant W
// ---------------------------------------------------------------------------
static __device__ __half g_x16[33554432];   // 8192 * 4096
static __device__ __half g_w16[67108864];   // 16384 * 4096

#define BM 128
#define BN 256
#define BK 64
#define STAGES 4
#define A_BYTES 16384            // 128 rows * 64 halves * 2B (row = 128B)
#define B_BYTES 32768            // 256 rows * 128B
#define STAGE_BYTES 49152        // A + B

// ---------------------------------------------------------------------------
// PTX helpers (plain sm_90-safe instructions only — harness targets sm_103
// without the 'a' feature suffix, so tcgen05/TMA-arch ops won't assemble)
// ---------------------------------------------------------------------------
__device__ __forceinline__ uint32_t cvta_shared(const void* p) {
    uint32_t a;
    asm("{ .reg .u64 t; cvta.to.shared.u64 t, %1; cvt.u32.u64 %0, t; }"
        : "=r"(a) : "l"(p));
    return a;
}
__device__ __forceinline__ void cp_async16(uint32_t dst, const void* src) {
    asm volatile("cp.async.cg.shared.global [%0], [%1], 16;"
                 :: "r"(dst), "l"(src));
}
__device__ __forceinline__ void cp_commit() {
    asm volatile("cp.async.commit_group;" ::: "memory");
}
__device__ __forceinline__ void cp_wait2() {
    asm volatile("cp.async.wait_group 2;" ::: "memory");
}
__device__ __forceinline__ void ldsm_x4(uint32_t* r, uint32_t addr) {
    asm volatile("ldmatrix.sync.aligned.m8n8.x4.shared.b16 {%0,%1,%2,%3}, [%4];"
                 : "=r"(r[0]), "=r"(r[1]), "=r"(r[2]), "=r"(r[3]) : "r"(addr));
}
__device__ __forceinline__ void mma16816(float* c, const uint32_t* a, const uint32_t* b) {
    asm volatile(
        "mma.sync.aligned.m16n8k16.row.col.f32.f16.f16.f32 "
        "{%0,%1,%2,%3}, {%4,%5,%6,%7}, {%8,%9}, {%0,%1,%2,%3};"
        : "+f"(c[0]), "+f"(c[1]), "+f"(c[2]), "+f"(c[3])
        : "r"(a[0]), "r"(a[1]), "r"(a[2]), "r"(a[3]), "r"(b[0]), "r"(b[1]));
}

// ---------------------------------------------------------------------------
// Conversion kernels
// ---------------------------------------------------------------------------
__global__ void convert_x_kernel(const float4* __restrict__ x, long long n4) {
    uint2* o = reinterpret_cast<uint2*>(g_x16);
    long long stride = (long long)gridDim.x * blockDim.x;
    for (long long i = (long long)blockIdx.x * blockDim.x + threadIdx.x; i < n4; i += stride) {
        float4 v = x[i];
        __half2 h0 = __floats2half2_rn(v.x, v.y);
        __half2 h1 = __floats2half2_rn(v.z, v.w);
        uint2 u;
        u.x = *reinterpret_cast<uint32_t*>(&h0);
        u.y = *reinterpret_cast<uint32_t*>(&h1);
        o[i] = u;
    }
}

// W dequant: w16[n,k] = fp16( w[n,k] * scale_inv[n/128, k/128] )
__global__ void convert_w_kernel(const float4* __restrict__ w, const float* __restrict__ sc,
                                 int K, int N) {
    int K4 = K >> 2;
    int KB = K >> 7;
    int k4 = blockIdx.x * blockDim.x + threadIdx.x;
    int n  = blockIdx.y;
    if (k4 >= K4) return;
    long long i = (long long)n * K4 + k4;
    float s = __ldg(sc + (n >> 7) * KB + (k4 >> 5));
    float4 v = w[i];
    __half2 h0 = __floats2half2_rn(v.x * s, v.y * s);
    __half2 h1 = __floats2half2_rn(v.z * s, v.w * s);
    uint2 u;
    u.x = *reinterpret_cast<uint32_t*>(&h0);
    u.y = *reinterpret_cast<uint32_t*>(&h1);
    reinterpret_cast<uint2*>(g_w16)[i] = u;
}

// ---------------------------------------------------------------------------
// HMMA GEMM: out[m,n] = sum_k x16[m,k] * w16[n,k] + bias[n]
// 128x256 tile/CTA, BK=64, 4-stage cp.async pipeline (192KB smem), 8 warps
// in a 2x4 grid -> warp tile 64x64, mma.sync.m16n8k16, f32 accum in regs.
// ---------------------------------------------------------------------------
__global__ void __launch_bounds__(256, 1)
gemm_f16_kernel(const float* __restrict__ bias, float* __restrict__ out,
                int M, int N, int K, int NT) {
    extern __shared__ char smem[];
    const uint32_t sbase = cvta_shared(smem);
    const int tid  = threadIdx.x;
    const int warp = tid >> 5;
    const int lane = tid & 31;

    // Grouped raster: groups of 8 M-tiles -> per-wave L2 working set small
    int bid = blockIdx.x;
    int tg  = NT << 3;
    int gq  = bid / tg;
    int rem = bid % tg;
    int mt  = (gq << 3) + (rem & 7);
    int nt  = rem >> 3;

    const __half* Ag = g_x16 + (size_t)mt * BM * K;
    const __half* Bg = g_w16 + (size_t)nt * BN * K;
    const int NKT = K / BK;

    // ---- cp.async per-thread offsets ----
    // A: 1024 16B chunks (4/thread); B: 2048 chunks (8/thread). Row = 128B.
    uint32_t sAofs[4], gAofs[4];
#pragma unroll
    for (int i = 0; i < 4; i++) {
        int chunk = tid + (i << 8);
        int row   = chunk >> 3;
        int cc    = chunk & 7;
        uint32_t so = (uint32_t)(row * 128 + cc * 16);
        sAofs[i] = so ^ ((so >> 3) & 0x70);
        gAofs[i] = (uint32_t)(row * K + cc * 8);
    }
    uint32_t sBofs[8], gBofs[8];
#pragma unroll
    for (int i = 0; i < 8; i++) {
        int chunk = tid + (i << 8);
        int row   = chunk >> 3;
        int cc    = chunk & 7;
        uint32_t so = (uint32_t)(row * 128 + cc * 16);
        sBofs[i] = so ^ ((so >> 3) & 0x70);
        gBofs[i] = (uint32_t)(row * K + cc * 8);
    }
    auto load_stage = [&](int s) {
        uint32_t sb = sbase + (uint32_t)(s & (STAGES - 1)) * STAGE_BYTES;
        const __half* ga = Ag + s * BK;
        const __half* gb = Bg + s * BK;
#pragma unroll
        for (int i = 0; i < 4; i++)
            cp_async16(sb + sAofs[i], ga + gAofs[i]);
#pragma unroll
        for (int i = 0; i < 8; i++)
            cp_async16(sb + A_BYTES + sBofs[i], gb + gBofs[i]);
    };

    for (int s = 0; s < STAGES - 1; s++) { load_stage(s); cp_commit(); }

    // ---- per-lane ldmatrix address components ----
    const int wm = warp & 1;             // 0..1 -> M offset wm*64
    const int wn = warp >> 1;            // 0..3 -> N offset wn*64
    // A: 4 m16 frags
    uint32_t aoff[4], acx[4];
    const uint32_t ahi = (uint32_t)((lane >> 4) << 4);
#pragma unroll
    for (int mi = 0; mi < 4; mi++) {
        int row = wm * 64 + mi * 16 + (lane & 15);
        aoff[mi] = (uint32_t)(row * 128);
        acx[mi]  = (uint32_t)((row & 7) << 4);
    }
    // B: 4 n16 frag-pairs
    uint32_t boff[4], bcx[4];
    const uint32_t bhi = (uint32_t)(((lane >> 3) & 1) << 4);
#pragma unroll
    for (int bp = 0; bp < 4; bp++) {
        int row = wn * 64 + bp * 16 + (lane & 7) + ((lane >> 4) << 3);
        boff[bp] = (uint32_t)(row * 128);
        bcx[bp]  = (uint32_t)((row & 7) << 4);
    }

    float c[4][8][4];
#pragma unroll
    for (int mi = 0; mi < 4; mi++)
#pragma unroll
        for (int f = 0; f < 8; f++)
#pragma unroll
            for (int r = 0; r < 4; r++) c[mi][f][r] = 0.0f;

    for (int kt = 0; kt < NKT; ++kt) {
        cp_wait2();                 // stage kt landed
        __syncthreads();

        int sp = kt + STAGES - 1;   // issue next loads first, then compute
        if (sp < NKT) load_stage(sp);
        cp_commit();                // commit (possibly empty) to keep counts

        uint32_t sA = sbase + (uint32_t)(kt & (STAGES - 1)) * STAGE_BYTES;
        uint32_t sB = sA + A_BYTES;
#pragma unroll
        for (int ks = 0; ks < 4; ks++) {
            uint32_t a[4][4], b[4][4];
#pragma unroll
            for (int mi = 0; mi < 4; mi++)
                ldsm_x4(a[mi], sA + aoff[mi] + ((ks * 32 + ahi) ^ acx[mi]));
#pragma unroll
            for (int bp = 0; bp < 4; bp++)
                ldsm_x4(b[bp], sB + boff[bp] + ((ks * 32 + bhi) ^ bcx[bp]));
#pragma unroll
            for (int mi = 0; mi < 4; mi++)
#pragma unroll
                for (int bp = 0; bp < 4; bp++) {
                    mma16816(c[mi][2 * bp + 0], a[mi], b[bp] + 0);
                    mma16816(c[mi][2 * bp + 1], a[mi], b[bp] + 2);
                }
        }
    }

    // ---- epilogue: add bias, store float2 pairs ----
    const int mbase = mt * BM + wm * 64 + (lane >> 2);
    const int nbase = nt * BN + wn * 64 + (lane & 3) * 2;
    float bb[8][2];
#pragma unroll
    for (int f = 0; f < 8; f++) {
        bb[f][0] = __ldg(bias + nbase + f * 8);
        bb[f][1] = __ldg(bias + nbase + f * 8 + 1);
    }
#pragma unroll
    for (int mi = 0; mi < 4; mi++) {
        int m0 = mbase + mi * 16;
#pragma unroll
        for (int f = 0; f < 8; f++) {
            int n0 = nbase + f * 8;
            float2 v0 = make_float2(c[mi][f][0] + bb[f][0], c[mi][f][1] + bb[f][1]);
            float2 v1 = make_float2(c[mi][f][2] + bb[f][0], c[mi][f][3] + bb[f][1]);
            *reinterpret_cast<float2*>(out + (size_t)m0 * N + n0)       = v0;
            *reinterpret_cast<float2*>(out + (size_t)(m0 + 8) * N + n0) = v1;
        }
    }
}

// ---------------------------------------------------------------------------
// Launch
// ---------------------------------------------------------------------------
extern "C" void kernel_launch(void* const* d_in, const int* in_sizes, int n_in,
                              void* d_out, int out_size) {
    const float* x    = (const float*)d_in[0];
    const float* w    = (const float*)d_in[1];
    const float* sc   = (const float*)d_in[2];
    const float* bias = (const float*)d_in[3];
    float* out = (float*)d_out;

    int N = in_sizes[3];
    int K = in_sizes[1] / N;
    int M = in_sizes[0] / K;

    convert_x_kernel<<<8192, 256>>>((const float4*)x, (long long)M * K / 4);

    dim3 gw((K / 4 + 255) / 256, N);
    convert_w_kernel<<<gw, 256>>>((const float4*)w, sc, K, N);

    int MT = M / BM, NT = N / BN;
    size_t smem_bytes = (size_t)STAGES * STAGE_BYTES;
    cudaFuncSetAttribute(gemm_f16_kernel,
                         cudaFuncAttributeMaxDynamicSharedMemorySize, (int)smem_bytes);
    gemm_f16_kernel<<<MT * NT, 256, smem_bytes>>>(bias, out, M, N, K, NT);
}

// round 10
// speedup vs baseline: 1.2821x; 1.0953x over previous
#include <cuda_runtime.h>
#include <cuda_fp16.h>
#include <stdint.h>

// ---------------------------------------------------------------------------
// Static device scratch (allocation-free rule): fp16 copies of x and dequant W
// ---------------------------------------------------------------------------
static __device__ __half g_x16[33554432];   // 8192 * 4096
static __device__ __half g_w16[67108864];   // 16384 * 4096

#define BM 128
#define BN 128
#define BK 64
#define STAGES 3
#define A_BYTES 16384            // 128 rows * 64 halves * 2B (row = 128B)
#define STAGE_BYTES 32768        // A + B

// ---------------------------------------------------------------------------
// PTX helpers (plain sm_90-safe instructions only — harness targets sm_103
// without the 'a' feature suffix, so tcgen05/TMA-arch ops won't assemble)
// ---------------------------------------------------------------------------
__device__ __forceinline__ uint32_t cvta_shared(const void* p) {
    uint32_t a;
    asm("{ .reg .u64 t; cvta.to.shared.u64 t, %1; cvt.u32.u64 %0, t; }"
        : "=r"(a) : "l"(p));
    return a;
}
__device__ __forceinline__ void cp_async16(uint32_t dst, const void* src) {
    asm volatile("cp.async.cg.shared.global [%0], [%1], 16;"
                 :: "r"(dst), "l"(src));
}
__device__ __forceinline__ void cp_commit() {
    asm volatile("cp.async.commit_group;" ::: "memory");
}
__device__ __forceinline__ void cp_wait1() {
    asm volatile("cp.async.wait_group 1;" ::: "memory");
}
__device__ __forceinline__ void ldsm_x4(uint32_t* r, uint32_t addr) {
    asm volatile("ldmatrix.sync.aligned.m8n8.x4.shared.b16 {%0,%1,%2,%3}, [%4];"
                 : "=r"(r[0]), "=r"(r[1]), "=r"(r[2]), "=r"(r[3]) : "r"(addr));
}
__device__ __forceinline__ void mma16816(float* c, const uint32_t* a, const uint32_t* b) {
    asm volatile(
        "mma.sync.aligned.m16n8k16.row.col.f32.f16.f16.f32 "
        "{%0,%1,%2,%3}, {%4,%5,%6,%7}, {%8,%9}, {%0,%1,%2,%3};"
        : "+f"(c[0]), "+f"(c[1]), "+f"(c[2]), "+f"(c[3])
        : "r"(a[0]), "r"(a[1]), "r"(a[2]), "r"(a[3]), "r"(b[0]), "r"(b[1]));
}

// ---------------------------------------------------------------------------
// Conversion kernels
// ---------------------------------------------------------------------------
__global__ void convert_x_kernel(const float4* __restrict__ x, long long n4) {
    uint2* o = reinterpret_cast<uint2*>(g_x16);
    long long stride = (long long)gridDim.x * blockDim.x;
    for (long long i = (long long)blockIdx.x * blockDim.x + threadIdx.x; i < n4; i += stride) {
        float4 v = x[i];
        __half2 h0 = __floats2half2_rn(v.x, v.y);
        __half2 h1 = __floats2half2_rn(v.z, v.w);
        uint2 u;
        u.x = *reinterpret_cast<uint32_t*>(&h0);
        u.y = *reinterpret_cast<uint32_t*>(&h1);
        o[i] = u;
    }
}

// W dequant: w16[n,k] = fp16( w[n,k] * scale_inv[n/128, k/128] )
__global__ void convert_w_kernel(const float4* __restrict__ w, const float* __restrict__ sc,
                                 int K, int N) {
    int K4 = K >> 2;
    int KB = K >> 7;
    int k4 = blockIdx.x * blockDim.x + threadIdx.x;
    int n  = blockIdx.y;
    if (k4 >= K4) return;
    long long i = (long long)n * K4 + k4;
    float s = __ldg(sc + (n >> 7) * KB + (k4 >> 5));
    float4 v = w[i];
    __half2 h0 = __floats2half2_rn(v.x * s, v.y * s);
    __half2 h1 = __floats2half2_rn(v.z * s, v.w * s);
    uint2 u;
    u.x = *reinterpret_cast<uint32_t*>(&h0);
    u.y = *reinterpret_cast<uint32_t*>(&h1);
    reinterpret_cast<uint2*>(g_w16)[i] = u;
}

// ---------------------------------------------------------------------------
// HMMA GEMM: out[m,n] = sum_k x16[m,k] * w16[n,k] + bias[n]
// 128x128 tile/CTA, 4 warps (2x2 grid, warp tile 64x64), BK=64, 3-stage
// cp.async pipeline (96KB smem) -> 2 CTAs/SM for cross-CTA bubble hiding.
// ---------------------------------------------------------------------------
__global__ void __launch_bounds__(128, 2)
gemm_f16_kernel(const float* __restrict__ bias, float* __restrict__ out,
                int M, int N, int K, int NT) {
    extern __shared__ char smem[];
    const uint32_t sbase = cvta_shared(smem);
    const int tid  = threadIdx.x;
    const int warp = tid >> 5;
    const int lane = tid & 31;

    // Grouped raster: groups of 8 M-tiles; the 8 same-nt CTAs are adjacent
    // bids -> co-resident -> B tiles L2-shared.
    int bid = blockIdx.x;
    int tg  = NT << 3;
    int gq  = bid / tg;
    int rem = bid % tg;
    int mt  = (gq << 3) + (rem & 7);
    int nt  = rem >> 3;

    const __half* Ag = g_x16 + (size_t)mt * BM * K;
    const __half* Bg = g_w16 + (size_t)nt * BN * K;
    const int NKT = K / BK;

    // ---- cp.async per-thread offsets ----
    // A: 1024 16B chunks over 128 threads = 8/thread; B identical. Row = 128B.
    uint32_t sofs[8], gofs[8];
#pragma unroll
    for (int i = 0; i < 8; i++) {
        int chunk = tid + (i << 7);      // 0..1023
        int row   = chunk >> 3;          // 0..127
        int cc    = chunk & 7;           // 16B column chunk
        uint32_t so = (uint32_t)(row * 128 + cc * 16);
        sofs[i] = so ^ ((so >> 3) & 0x70);          // SW128 swizzle
        gofs[i] = (uint32_t)(row * K + cc * 8);     // elements
    }
    auto load_stage = [&](int s, int slot) {
        uint32_t sb = sbase + (uint32_t)slot * STAGE_BYTES;
        const __half* ga = Ag + s * BK;
        const __half* gb = Bg + s * BK;
#pragma unroll
        for (int i = 0; i < 8; i++) {
            cp_async16(sb + sofs[i],           ga + gofs[i]);
            cp_async16(sb + A_BYTES + sofs[i], gb + gofs[i]);
        }
    };

    load_stage(0, 0); cp_commit();
    load_stage(1, 1); cp_commit();

    // ---- per-lane ldmatrix address components (warp tile 64x64) ----
    const int wm = warp & 1;             // 0..1 -> M offset wm*64
    const int wn = warp >> 1;            // 0..1 -> N offset wn*64
    uint32_t aoff[4], acx[4];
    const uint32_t ahi = (uint32_t)((lane >> 4) << 4);
#pragma unroll
    for (int mi = 0; mi < 4; mi++) {
        int row = wm * 64 + mi * 16 + (lane & 15);
        aoff[mi] = (uint32_t)(row * 128);
        acx[mi]  = (uint32_t)((row & 7) << 4);
    }
    uint32_t boff[4], bcx[4];
    const uint32_t bhi = (uint32_t)(((lane >> 3) & 1) << 4);
#pragma unroll
    for (int bp = 0; bp < 4; bp++) {
        int row = wn * 64 + bp * 16 + (lane & 7) + ((lane >> 4) << 3);
        boff[bp] = (uint32_t)(row * 128);
        bcx[bp]  = (uint32_t)((row & 7) << 4);
    }

    float c[4][8][4];
#pragma unroll
    for (int mi = 0; mi < 4; mi++)
#pragma unroll
        for (int f = 0; f < 8; f++)
#pragma unroll
            for (int r = 0; r < 4; r++) c[mi][f][r] = 0.0f;

    int slot = 0, slot2 = 2;             // slot = kt%3, slot2 = (kt+2)%3
    for (int kt = 0; kt < NKT; ++kt) {
        cp_wait1();                 // stage kt landed (kt+1 still in flight)
        __syncthreads();

        int sp = kt + 2;            // issue next loads first, then compute
        if (sp < NKT) load_stage(sp, slot2);
        cp_commit();                // commit (possibly empty) to keep counts

        uint32_t sA = sbase + (uint32_t)slot * STAGE_BYTES;
        uint32_t sB = sA + A_BYTES;
#pragma unroll
        for (int ks = 0; ks < 4; ks++) {
            uint32_t a[4][4], b[4][4];
#pragma unroll
            for (int mi = 0; mi < 4; mi++)
                ldsm_x4(a[mi], sA + aoff[mi] + ((ks * 32 + ahi) ^ acx[mi]));
#pragma unroll
            for (int bp = 0; bp < 4; bp++)
                ldsm_x4(b[bp], sB + boff[bp] + ((ks * 32 + bhi) ^ bcx[bp]));
#pragma unroll
            for (int mi = 0; mi < 4; mi++)
#pragma unroll
                for (int bp = 0; bp < 4; bp++) {
                    mma16816(c[mi][2 * bp + 0], a[mi], b[bp] + 0);
                    mma16816(c[mi][2 * bp + 1], a[mi], b[bp] + 2);
                }
        }
        slot  = (slot  == 2) ? 0 : slot  + 1;
        slot2 = (slot2 == 2) ? 0 : slot2 + 1;
    }

    // ---- epilogue: add bias, store float2 pairs ----
    const int mbase = mt * BM + wm * 64 + (lane >> 2);
    const int nbase = nt * BN + wn * 64 + (lane & 3) * 2;
    float bb[8][2];
#pragma unroll
    for (int f = 0; f < 8; f++) {
        bb[f][0] = __ldg(bias + nbase + f * 8);
        bb[f][1] = __ldg(bias + nbase + f * 8 + 1);
    }
#pragma unroll
    for (int mi = 0; mi < 4; mi++) {
        int m0 = mbase + mi * 16;
#pragma unroll
        for (int f = 0; f < 8; f++) {
            int n0 = nbase + f * 8;
            float2 v0 = make_float2(c[mi][f][0] + bb[f][0], c[mi][f][1] + bb[f][1]);
            float2 v1 = make_float2(c[mi][f][2] + bb[f][0], c[mi][f][3] + bb[f][1]);
            *reinterpret_cast<float2*>(out + (size_t)m0 * N + n0)       = v0;
            *reinterpret_cast<float2*>(out + (size_t)(m0 + 8) * N + n0) = v1;
        }
    }
}

// ---------------------------------------------------------------------------
// Launch
// ---------------------------------------------------------------------------
extern "C" void kernel_launch(void* const* d_in, const int* in_sizes, int n_in,
                              void* d_out, int out_size) {
    const float* x    = (const float*)d_in[0];
    const float* w    = (const float*)d_in[1];
    const float* sc   = (const float*)d_in[2];
    const float* bias = (const float*)d_in[3];
    float* out = (float*)d_out;

    int N = in_sizes[3];
    int K = in_sizes[1] / N;
    int M = in_sizes[0] / K;

    convert_x_kernel<<<8192, 256>>>((const float4*)x, (long long)M * K / 4);

    dim3 gw((K / 4 + 255) / 256, N);
    convert_w_kernel<<<gw, 256>>>((const float4*)w, sc, K, N);

    int MT = M / BM, NT = N / BN;
    size_t smem_bytes = (size_t)STAGES * STAGE_BYTES;   // 96 KB
    cudaFuncSetAttribute(gemm_f16_kernel,
                         cudaFuncAttributeMaxDynamicSharedMemorySize, (int)smem_bytes);
    gemm_f16_kernel<<<MT * NT, 128, smem_bytes>>>(bias, out, M, N, K, NT);
}

// round 13
// speedup vs baseline: 1.4452x; 1.1272x over previous
#include <cuda_runtime.h>
#include <cuda_fp16.h>
#include <stdint.h>

// ---------------------------------------------------------------------------
// Static device scratch: fp16 x and dequant W, stored in PRE-SWIZZLED tile
// format = exact smem image. Tile = 128 rows x 64 halves (16KB), SW128
// swizzle applied. g_x16 tile index = mt*(K/64)+kt ; g_w16 = nt*(K/64)+kt.
// ---------------------------------------------------------------------------
static __device__ __half g_x16[33554432];   // 8192 * 4096
static __device__ __half g_w16[67108864];   // 16384 * 4096

#define BM 128
#define BN 128
#define BK 64
#define STAGES 3
#define TILE_HALVES 8192         // 128*64
#define TILE_BYTES 16384
#define A_BYTES 16384
#define STAGE_BYTES 32768        // A + B
#define SMEM_TILE_OFF 1024       // mbars live below

// ---------------------------------------------------------------------------
// PTX helpers (plain sm_90-safe only: harness targets sm_103 w/o 'a' suffix;
// tcgen05/arch ops won't assemble, but cp.async.bulk/mbarrier are sm_90 base)
// ---------------------------------------------------------------------------
__device__ __forceinline__ uint32_t cvta_shared(const void* p) {
    uint32_t a;
    asm("{ .reg .u64 t; cvta.to.shared.u64 t, %1; cvt.u32.u64 %0, t; }"
        : "=r"(a) : "l"(p));
    return a;
}
__device__ __forceinline__ void mbar_init(uint32_t mbar, uint32_t cnt) {
    asm volatile("mbarrier.init.shared.b64 [%0], %1;"
                 :: "r"(mbar), "r"(cnt) : "memory");
}
__device__ __forceinline__ void mbar_expect_tx(uint32_t mbar, uint32_t bytes) {
    asm volatile("mbarrier.arrive.expect_tx.shared.b64 _, [%0], %1;"
                 :: "r"(mbar), "r"(bytes) : "memory");
}
__device__ __forceinline__ void mbar_wait(uint32_t mbar, uint32_t parity) {
    asm volatile(
        "{\n\t"
        ".reg .pred P;\n\t"
        "WL_%=:\n\t"
        "mbarrier.try_wait.parity.acquire.cta.shared::cta.b64 P, [%0], %1, 0x989680;\n\t"
        "@!P bra WL_%=;\n\t"
        "}"
        :: "r"(mbar), "r"(parity) : "memory");
}
__device__ __forceinline__ void bulk_g2s(uint32_t dst, const void* src,
                                         uint32_t bytes, uint32_t mbar) {
    asm volatile(
        "cp.async.bulk.shared::cluster.global.mbarrier::complete_tx::bytes "
        "[%0], [%1], %2, [%3];"
        :: "r"(dst), "l"(src), "r"(bytes), "r"(mbar) : "memory");
}
__device__ __forceinline__ void ldsm_x4(uint32_t* r, uint32_t addr) {
    asm volatile("ldmatrix.sync.aligned.m8n8.x4.shared.b16 {%0,%1,%2,%3}, [%4];"
                 : "=r"(r[0]), "=r"(r[1]), "=r"(r[2]), "=r"(r[3]) : "r"(addr));
}
__device__ __forceinline__ void mma16816(float* c, const uint32_t* a, const uint32_t* b) {
    asm volatile(
        "mma.sync.aligned.m16n8k16.row.col.f32.f16.f16.f32 "
        "{%0,%1,%2,%3}, {%4,%5,%6,%7}, {%8,%9}, {%0,%1,%2,%3};"
        : "+f"(c[0]), "+f"(c[1]), "+f"(c[2]), "+f"(c[3])
        : "r"(a[0]), "r"(a[1]), "r"(a[2]), "r"(a[3]), "r"(b[0]), "r"(b[1]));
}

// ---------------------------------------------------------------------------
// Conversion kernels: write swizzled tile-major layout (one 16B chunk/thread)
// ---------------------------------------------------------------------------
__global__ void convert_x_kernel(const float4* __restrict__ x, int K, long long nchunks) {
    long long idx = (long long)blockIdx.x * blockDim.x + threadIdx.x;
    if (idx >= nchunks) return;
    int kc8 = K >> 3;                         // 16B chunks per row
    int m  = (int)(idx / kc8);
    int kc = (int)(idx - (long long)m * kc8);
    float4 f0 = x[(long long)m * (K >> 2) + kc * 2];
    float4 f1 = x[(long long)m * (K >> 2) + kc * 2 + 1];
    __half2 h0 = __floats2half2_rn(f0.x, f0.y);
    __half2 h1 = __floats2half2_rn(f0.z, f0.w);
    __half2 h2 = __floats2half2_rn(f1.x, f1.y);
    __half2 h3 = __floats2half2_rn(f1.z, f1.w);
    uint4 u;
    u.x = *reinterpret_cast<uint32_t*>(&h0);
    u.y = *reinterpret_cast<uint32_t*>(&h1);
    u.z = *reinterpret_cast<uint32_t*>(&h2);
    u.w = *reinterpret_cast<uint32_t*>(&h3);
    int tile = (m >> 7) * (K >> 6) + (kc >> 3);
    uint32_t so = (uint32_t)(((m & 127) << 7) + ((kc & 7) << 4));
    so ^= ((so >> 3) & 0x70);
    *reinterpret_cast<uint4*>(
        reinterpret_cast<char*>(g_x16) + (size_t)tile * TILE_BYTES + so) = u;
}

__global__ void convert_w_kernel(const float4* __restrict__ w, const float* __restrict__ sc,
                                 int K, long long nchunks) {
    long long idx = (long long)blockIdx.x * blockDim.x + threadIdx.x;
    if (idx >= nchunks) return;
    int kc8 = K >> 3;
    int n  = (int)(idx / kc8);
    int kc = (int)(idx - (long long)n * kc8);
    int KB = K >> 7;
    float s = __ldg(sc + (n >> 7) * KB + (kc >> 4));
    float4 f0 = w[(long long)n * (K >> 2) + kc * 2];
    float4 f1 = w[(long long)n * (K >> 2) + kc * 2 + 1];
    __half2 h0 = __floats2half2_rn(f0.x * s, f0.y * s);
    __half2 h1 = __floats2half2_rn(f0.z * s, f0.w * s);
    __half2 h2 = __floats2half2_rn(f1.x * s, f1.y * s);
    __half2 h3 = __floats2half2_rn(f1.z * s, f1.w * s);
    uint4 u;
    u.x = *reinterpret_cast<uint32_t*>(&h0);
    u.y = *reinterpret_cast<uint32_t*>(&h1);
    u.z = *reinterpret_cast<uint32_t*>(&h2);
    u.w = *reinterpret_cast<uint32_t*>(&h3);
    int tile = (n >> 7) * (K >> 6) + (kc >> 3);
    uint32_t so = (uint32_t)(((n & 127) << 7) + ((kc & 7) << 4));
    so ^= ((so >> 3) & 0x70);
    *reinterpret_cast<uint4*>(
        reinterpret_cast<char*>(g_w16) + (size_t)tile * TILE_BYTES + so) = u;
}

// ---------------------------------------------------------------------------
// HMMA GEMM: 128x128 tile/CTA, 4 warps (2x2, warp tile 64x64), BK=64,
// 3-stage pipeline fed by single-thread cp.async.bulk + mbarrier.
// 2 CTAs/SM (96KB+1KB smem each) for cross-CTA bubble hiding.
// ---------------------------------------------------------------------------
__global__ void __launch_bounds__(128, 2)
gemm_f16_kernel(const float* __restrict__ bias, float* __restrict__ out,
                int M, int N, int K, int NT) {
    extern __shared__ char smem[];
    const uint32_t sbase = cvta_shared(smem);
    const int tid  = threadIdx.x;
    const int warp = tid >> 5;
    const int lane = tid & 31;

    // Grouped raster: groups of 8 M-tiles; same-nt CTAs adjacent -> L2 share B
    int bid = blockIdx.x;
    int tg  = NT << 3;
    int gq  = bid / tg;
    int rem = bid % tg;
    int mt  = (gq << 3) + (rem & 7);
    int nt  = rem >> 3;

    const int NKT = K / BK;
    const __half* Ag = g_x16 + (size_t)mt * NKT * TILE_HALVES;
    const __half* Bg = g_w16 + (size_t)nt * NKT * TILE_HALVES;

    if (tid == 0) {
        mbar_init(sbase + 0,  1);
        mbar_init(sbase + 8,  1);
        mbar_init(sbase + 16, 1);
    }
    __syncthreads();

    auto load_stage = [&](int s, int slot) {
        uint32_t mb = sbase + (uint32_t)(slot << 3);
        uint32_t sd = sbase + SMEM_TILE_OFF + (uint32_t)slot * STAGE_BYTES;
        mbar_expect_tx(mb, STAGE_BYTES);
        bulk_g2s(sd,           Ag + (size_t)s * TILE_HALVES, TILE_BYTES, mb);
        bulk_g2s(sd + A_BYTES, Bg + (size_t)s * TILE_HALVES, TILE_BYTES, mb);
    };
    if (tid == 0) { load_stage(0, 0); load_stage(1, 1); }

    // ---- per-lane ldmatrix address components (warp tile 64x64) ----
    const int wm = warp & 1;
    const int wn = warp >> 1;
    uint32_t aoff[4], acx[4];
    const uint32_t ahi = (uint32_t)((lane >> 4) << 4);
#pragma unroll
    for (int mi = 0; mi < 4; mi++) {
        int row = wm * 64 + mi * 16 + (lane & 15);
        aoff[mi] = (uint32_t)(row * 128);
        acx[mi]  = (uint32_t)((row & 7) << 4);
    }
    uint32_t boff[4], bcx[4];
    const uint32_t bhi = (uint32_t)(((lane >> 3) & 1) << 4);
#pragma unroll
    for (int bp = 0; bp < 4; bp++) {
        int row = wn * 64 + bp * 16 + (lane & 7) + ((lane >> 4) << 3);
        boff[bp] = (uint32_t)(row * 128);
        bcx[bp]  = (uint32_t)((row & 7) << 4);
    }

    float c[4][8][4];
#pragma unroll
    for (int mi = 0; mi < 4; mi++)
#pragma unroll
        for (int f = 0; f < 8; f++)
#pragma unroll
            for (int r = 0; r < 4; r++) c[mi][f][r] = 0.0f;

    uint32_t pbits = 0;
    int slot = 0, slot2 = 2;             // slot = kt%3, slot2 = (kt+2)%3
    for (int kt = 0; kt < NKT; ++kt) {
        __syncthreads();            // all warps done with slot2's prior data
        int sp = kt + 2;
        if (tid == 0 && sp < NKT) load_stage(sp, slot2);

        uint32_t par = (pbits >> slot) & 1;
        mbar_wait(sbase + (uint32_t)(slot << 3), par);
        pbits ^= (1u << slot);

        uint32_t sA = sbase + SMEM_TILE_OFF + (uint32_t)slot * STAGE_BYTES;
        uint32_t sB = sA + A_BYTES;
#pragma unroll
        for (int ks = 0; ks < 4; ks++) {
            uint32_t a[4][4], b[4][4];
#pragma unroll
            for (int mi = 0; mi < 4; mi++)
                ldsm_x4(a[mi], sA + aoff[mi] + ((ks * 32 + ahi) ^ acx[mi]));
#pragma unroll
            for (int bp = 0; bp < 4; bp++)
                ldsm_x4(b[bp], sB + boff[bp] + ((ks * 32 + bhi) ^ bcx[bp]));
#pragma unroll
            for (int mi = 0; mi < 4; mi++)
#pragma unroll
                for (int bp = 0; bp < 4; bp++) {
                    mma16816(c[mi][2 * bp + 0], a[mi], b[bp] + 0);
                    mma16816(c[mi][2 * bp + 1], a[mi], b[bp] + 2);
                }
        }
        slot  = (slot  == 2) ? 0 : slot  + 1;
        slot2 = (slot2 == 2) ? 0 : slot2 + 1;
    }

    // ---- epilogue: add bias, store float2 pairs ----
    const int mbase = mt * BM + wm * 64 + (lane >> 2);
    const int nbase = nt * BN + wn * 64 + (lane & 3) * 2;
    float bb[8][2];
#pragma unroll
    for (int f = 0; f < 8; f++) {
        bb[f][0] = __ldg(bias + nbase + f * 8);
        bb[f][1] = __ldg(bias + nbase + f * 8 + 1);
    }
#pragma unroll
    for (int mi = 0; mi < 4; mi++) {
        int m0 = mbase + mi * 16;
#pragma unroll
        for (int f = 0; f < 8; f++) {
            int n0 = nbase + f * 8;
            float2 v0 = make_float2(c[mi][f][0] + bb[f][0], c[mi][f][1] + bb[f][1]);
            float2 v1 = make_float2(c[mi][f][2] + bb[f][0], c[mi][f][3] + bb[f][1]);
            *reinterpret_cast<float2*>(out + (size_t)m0 * N + n0)       = v0;
            *reinterpret_cast<float2*>(out + (size_t)(m0 + 8) * N + n0) = v1;
        }
    }
}

// ---------------------------------------------------------------------------
// Launch
// ---------------------------------------------------------------------------
extern "C" void kernel_launch(void* const* d_in, const int* in_sizes, int n_in,
                              void* d_out, int out_size) {
    const float* x    = (const float*)d_in[0];
    const float* w    = (const float*)d_in[1];
    const float* sc   = (const float*)d_in[2];
    const float* bias = (const float*)d_in[3];
    float* out = (float*)d_out;

    int N = in_sizes[3];
    int K = in_sizes[1] / N;
    int M = in_sizes[0] / K;

    long long xchunks = (long long)M * K / 8;
    convert_x_kernel<<<(unsigned)((xchunks + 255) / 256), 256>>>((const float4*)x, K, xchunks);

    long long wchunks = (long long)N * K / 8;
    convert_w_kernel<<<(unsigned)((wchunks + 255) / 256), 256>>>((const float4*)w, sc, K, wchunks);

    int MT = M / BM, NT = N / BN;
    size_t smem_bytes = SMEM_TILE_OFF + (size_t)STAGES * STAGE_BYTES;  // 99328
    cudaFuncSetAttribute(gemm_f16_kernel,
                         cudaFuncAttributeMaxDynamicSharedMemorySize, (int)smem_bytes);
    gemm_f16_kernel<<<MT * NT, 128, smem_bytes>>>(bias, out, M, N, K, NT);
}

// round 14
// speedup vs baseline: 1.4868x; 1.0288x over previous
#include <cuda_runtime.h>
#include <cuda_fp16.h>
#include <stdint.h>

// ---------------------------------------------------------------------------
// Static device scratch: fp16 x and dequant W, stored in PRE-SWIZZLED tile
// format = exact smem image. Tile = 128 rows x 64 halves (16KB), SW128
// swizzle applied. g_x16 tile index = mt*(K/64)+kt ; g_w16 = nt*(K/64)+kt.
// ---------------------------------------------------------------------------
static __device__ __half g_x16[33554432];   // 8192 * 4096
static __device__ __half g_w16[67108864];   // 16384 * 4096

#define BM 128
#define BN 128
#define BK 64
#define STAGES 3
#define TILE_HALVES 8192         // 128*64
#define TILE_BYTES 16384
#define A_BYTES 16384
#define STAGE_BYTES 32768        // A + B
#define SMEM_TILE_OFF 1024       // mbars live below

// ---------------------------------------------------------------------------
// PTX helpers (plain sm_90-safe only: harness targets sm_103 w/o 'a' suffix;
// tcgen05/arch ops won't assemble, but cp.async.bulk/mbarrier are sm_90 base)
// ---------------------------------------------------------------------------
__device__ __forceinline__ uint32_t cvta_shared(const void* p) {
    uint32_t a;
    asm("{ .reg .u64 t; cvta.to.shared.u64 t, %1; cvt.u32.u64 %0, t; }"
        : "=r"(a) : "l"(p));
    return a;
}
__device__ __forceinline__ void mbar_init(uint32_t mbar, uint32_t cnt) {
    asm volatile("mbarrier.init.shared.b64 [%0], %1;"
                 :: "r"(mbar), "r"(cnt) : "memory");
}
__device__ __forceinline__ void mbar_expect_tx(uint32_t mbar, uint32_t bytes) {
    asm volatile("mbarrier.arrive.expect_tx.shared.b64 _, [%0], %1;"
                 :: "r"(mbar), "r"(bytes) : "memory");
}
__device__ __forceinline__ void mbar_arrive(uint32_t mbar) {
    asm volatile("mbarrier.arrive.shared.b64 _, [%0];"
                 :: "r"(mbar) : "memory");
}
__device__ __forceinline__ void mbar_wait(uint32_t mbar, uint32_t parity) {
    asm volatile(
        "{\n\t"
        ".reg .pred P;\n\t"
        "WL_%=:\n\t"
        "mbarrier.try_wait.parity.acquire.cta.shared::cta.b64 P, [%0], %1, 0x989680;\n\t"
        "@!P bra WL_%=;\n\t"
        "}"
        :: "r"(mbar), "r"(parity) : "memory");
}
__device__ __forceinline__ void bulk_g2s(uint32_t dst, const void* src,
                                         uint32_t bytes, uint32_t mbar) {
    asm volatile(
        "cp.async.bulk.shared::cluster.global.mbarrier::complete_tx::bytes "
        "[%0], [%1], %2, [%3];"
        :: "r"(dst), "l"(src), "r"(bytes), "r"(mbar) : "memory");
}
__device__ __forceinline__ void ldsm_x4(uint32_t* r, uint32_t addr) {
    asm volatile("ldmatrix.sync.aligned.m8n8.x4.shared.b16 {%0,%1,%2,%3}, [%4];"
                 : "=r"(r[0]), "=r"(r[1]), "=r"(r[2]), "=r"(r[3]) : "r"(addr));
}
__device__ __forceinline__ void mma16816(float* c, const uint32_t* a, const uint32_t* b) {
    asm volatile(
        "mma.sync.aligned.m16n8k16.row.col.f32.f16.f16.f32 "
        "{%0,%1,%2,%3}, {%4,%5,%6,%7}, {%8,%9}, {%0,%1,%2,%3};"
        : "+f"(c[0]), "+f"(c[1]), "+f"(c[2]), "+f"(c[3])
        : "r"(a[0]), "r"(a[1]), "r"(a[2]), "r"(a[3]), "r"(b[0]), "r"(b[1]));
}

// ---------------------------------------------------------------------------
// Conversion kernels: write swizzled tile-major layout (one 16B chunk/thread)
// ---------------------------------------------------------------------------
__global__ void convert_x_kernel(const float4* __restrict__ x, int K, long long nchunks) {
    long long idx = (long long)blockIdx.x * blockDim.x + threadIdx.x;
    if (idx >= nchunks) return;
    int kc8 = K >> 3;                         // 16B chunks per row
    int m  = (int)(idx / kc8);
    int kc = (int)(idx - (long long)m * kc8);
    float4 f0 = x[(long long)m * (K >> 2) + kc * 2];
    float4 f1 = x[(long long)m * (K >> 2) + kc * 2 + 1];
    __half2 h0 = __floats2half2_rn(f0.x, f0.y);
    __half2 h1 = __floats2half2_rn(f0.z, f0.w);
    __half2 h2 = __floats2half2_rn(f1.x, f1.y);
    __half2 h3 = __floats2half2_rn(f1.z, f1.w);
    uint4 u;
    u.x = *reinterpret_cast<uint32_t*>(&h0);
    u.y = *reinterpret_cast<uint32_t*>(&h1);
    u.z = *reinterpret_cast<uint32_t*>(&h2);
    u.w = *reinterpret_cast<uint32_t*>(&h3);
    int tile = (m >> 7) * (K >> 6) + (kc >> 3);
    uint32_t so = (uint32_t)(((m & 127) << 7) + ((kc & 7) << 4));
    so ^= ((so >> 3) & 0x70);
    *reinterpret_cast<uint4*>(
        reinterpret_cast<char*>(g_x16) + (size_t)tile * TILE_BYTES + so) = u;
}

__global__ void convert_w_kernel(const float4* __restrict__ w, const float* __restrict__ sc,
                                 int K, long long nchunks) {
    long long idx = (long long)blockIdx.x * blockDim.x + threadIdx.x;
    if (idx >= nchunks) return;
    int kc8 = K >> 3;
    int n  = (int)(idx / kc8);
    int kc = (int)(idx - (long long)n * kc8);
    int KB = K >> 7;
    float s = __ldg(sc + (n >> 7) * KB + (kc >> 4));
    float4 f0 = w[(long long)n * (K >> 2) + kc * 2];
    float4 f1 = w[(long long)n * (K >> 2) + kc * 2 + 1];
    __half2 h0 = __floats2half2_rn(f0.x * s, f0.y * s);
    __half2 h1 = __floats2half2_rn(f0.z * s, f0.w * s);
    __half2 h2 = __floats2half2_rn(f1.x * s, f1.y * s);
    __half2 h3 = __floats2half2_rn(f1.z * s, f1.w * s);
    uint4 u;
    u.x = *reinterpret_cast<uint32_t*>(&h0);
    u.y = *reinterpret_cast<uint32_t*>(&h1);
    u.z = *reinterpret_cast<uint32_t*>(&h2);
    u.w = *reinterpret_cast<uint32_t*>(&h3);
    int tile = (n >> 7) * (K >> 6) + (kc >> 3);
    uint32_t so = (uint32_t)(((n & 127) << 7) + ((kc & 7) << 4));
    so ^= ((so >> 3) & 0x70);
    *reinterpret_cast<uint4*>(
        reinterpret_cast<char*>(g_w16) + (size_t)tile * TILE_BYTES + so) = u;
}

// ---------------------------------------------------------------------------
// HMMA GEMM: 128x128 tile/CTA, 4 warps (2x2, warp tile 64x64), BK=64,
// 3-stage pipeline fed by single-thread cp.async.bulk + full/empty mbarriers
// (no __syncthreads in mainloop: warps arrive, only producer waits).
// 2 CTAs/SM for cross-CTA bubble hiding.
// ---------------------------------------------------------------------------
__global__ void __launch_bounds__(128, 2)
gemm_f16_kernel(const float* __restrict__ bias, float* __restrict__ out,
                int M, int N, int K, int NT) {
    extern __shared__ char smem[];
    const uint32_t sbase = cvta_shared(smem);
    const int tid  = threadIdx.x;
    const int warp = tid >> 5;
    const int lane = tid & 31;
    // producer = warp 3 lane 0 (hi-wid arbiter priority -> prompt load issue)
    const bool producer = (tid == 96);

    // Grouped raster: groups of 8 M-tiles; same-nt CTAs adjacent -> L2 share B
    int bid = blockIdx.x;
    int tg  = NT << 3;
    int gq  = bid / tg;
    int rem = bid % tg;
    int mt  = (gq << 3) + (rem & 7);
    int nt  = rem >> 3;

    const int NKT = K / BK;
    const __half* Ag = g_x16 + (size_t)mt * NKT * TILE_HALVES;
    const __half* Bg = g_w16 + (size_t)nt * NKT * TILE_HALVES;

    // mbars: full[s] at sbase + 8*s, empty[s] at sbase + 24 + 8*s
    if (producer) {
#pragma unroll
        for (int s = 0; s < 3; s++) {
            mbar_init(sbase + (uint32_t)(s << 3), 1);        // full
            mbar_init(sbase + 24u + (uint32_t)(s << 3), 4);  // empty (4 warps)
        }
    }
    __syncthreads();

    auto load_stage = [&](int s, int slot) {
        uint32_t mb = sbase + (uint32_t)(slot << 3);
        uint32_t sd = sbase + SMEM_TILE_OFF + (uint32_t)slot * STAGE_BYTES;
        mbar_expect_tx(mb, STAGE_BYTES);
        bulk_g2s(sd,           Ag + (size_t)s * TILE_HALVES, TILE_BYTES, mb);
        bulk_g2s(sd + A_BYTES, Bg + (size_t)s * TILE_HALVES, TILE_BYTES, mb);
    };
    if (producer) { load_stage(0, 0); load_stage(1, 1); }

    // ---- per-lane ldmatrix address components (warp tile 64x64) ----
    const int wm = warp & 1;
    const int wn = warp >> 1;
    uint32_t aoff[4], acx[4];
    const uint32_t ahi = (uint32_t)((lane >> 4) << 4);
#pragma unroll
    for (int mi = 0; mi < 4; mi++) {
        int row = wm * 64 + mi * 16 + (lane & 15);
        aoff[mi] = (uint32_t)(row * 128);
        acx[mi]  = (uint32_t)((row & 7) << 4);
    }
    uint32_t boff[4], bcx[4];
    const uint32_t bhi = (uint32_t)(((lane >> 3) & 1) << 4);
#pragma unroll
    for (int bp = 0; bp < 4; bp++) {
        int row = wn * 64 + bp * 16 + (lane & 7) + ((lane >> 4) << 3);
        boff[bp] = (uint32_t)(row * 128);
        bcx[bp]  = (uint32_t)((row & 7) << 4);
    }

    float c[4][8][4];
#pragma unroll
    for (int mi = 0; mi < 4; mi++)
#pragma unroll
        for (int f = 0; f < 8; f++)
#pragma unroll
            for (int r = 0; r < 4; r++) c[mi][f][r] = 0.0f;

    uint32_t pbits = 0;                  // per-warp full-barrier parity bits
    int slot = 0, slot2 = 2;             // slot = kt%3, slot2 = (kt+2)%3
    for (int kt = 0; kt < NKT; ++kt) {
        int sp = kt + 2;
        if (producer && sp < NKT) {
            if (sp >= 3)                 // slot reuse: wait all-warps empty arrive
                mbar_wait(sbase + 24u + (uint32_t)(slot2 << 3),
                          (uint32_t)((sp / 3 - 1) & 1));
            load_stage(sp, slot2);
        }

        uint32_t par = (pbits >> slot) & 1;
        mbar_wait(sbase + (uint32_t)(slot << 3), par);
        pbits ^= (1u << slot);

        uint32_t sA = sbase + SMEM_TILE_OFF + (uint32_t)slot * STAGE_BYTES;
        uint32_t sB = sA + A_BYTES;
#pragma unroll
        for (int ks = 0; ks < 4; ks++) {
            uint32_t a[4][4], b[4][4];
#pragma unroll
            for (int mi = 0; mi < 4; mi++)
                ldsm_x4(a[mi], sA + aoff[mi] + ((ks * 32 + ahi) ^ acx[mi]));
#pragma unroll
            for (int bp = 0; bp < 4; bp++)
                ldsm_x4(b[bp], sB + boff[bp] + ((ks * 32 + bhi) ^ bcx[bp]));
#pragma unroll
            for (int mi = 0; mi < 4; mi++)
#pragma unroll
                for (int bp = 0; bp < 4; bp++) {
                    mma16816(c[mi][2 * bp + 0], a[mi], b[bp] + 0);
                    mma16816(c[mi][2 * bp + 1], a[mi], b[bp] + 2);
                }
        }
        // warp done reading this slot: elected release-arrive on empty barrier
        __syncwarp();
        if (lane == 0) mbar_arrive(sbase + 24u + (uint32_t)(slot << 3));

        slot  = (slot  == 2) ? 0 : slot  + 1;
        slot2 = (slot2 == 2) ? 0 : slot2 + 1;
    }

    // ---- epilogue: add bias, store float2 pairs ----
    const int mbase = mt * BM + wm * 64 + (lane >> 2);
    const int nbase = nt * BN + wn * 64 + (lane & 3) * 2;
    float bb[8][2];
#pragma unroll
    for (int f = 0; f < 8; f++) {
        bb[f][0] = __ldg(bias + nbase + f * 8);
        bb[f][1] = __ldg(bias + nbase + f * 8 + 1);
    }
#pragma unroll
    for (int mi = 0; mi < 4; mi++) {
        int m0 = mbase + mi * 16;
#pragma unroll
        for (int f = 0; f < 8; f++) {
            int n0 = nbase + f * 8;
            float2 v0 = make_float2(c[mi][f][0] + bb[f][0], c[mi][f][1] + bb[f][1]);
            float2 v1 = make_float2(c[mi][f][2] + bb[f][0], c[mi][f][3] + bb[f][1]);
            *reinterpret_cast<float2*>(out + (size_t)m0 * N + n0)       = v0;
            *reinterpret_cast<float2*>(out + (size_t)(m0 + 8) * N + n0) = v1;
        }
    }
}

// ---------------------------------------------------------------------------
// Launch
// ---------------------------------------------------------------------------
extern "C" void kernel_launch(void* const* d_in, const int* in_sizes, int n_in,
                              void* d_out, int out_size) {
    const float* x    = (const float*)d_in[0];
    const float* w    = (const float*)d_in[1];
    const float* sc   = (const float*)d_in[2];
    const float* bias = (const float*)d_in[3];
    float* out = (float*)d_out;

    int N = in_sizes[3];
    int K = in_sizes[1] / N;
    int M = in_sizes[0] / K;

    long long xchunks = (long long)M * K / 8;
    convert_x_kernel<<<(unsigned)((xchunks + 255) / 256), 256>>>((const float4*)x, K, xchunks);

    long long wchunks = (long long)N * K / 8;
    convert_w_kernel<<<(unsigned)((wchunks + 255) / 256), 256>>>((const float4*)w, sc, K, wchunks);

    int MT = M / BM, NT = N / BN;
    size_t smem_bytes = SMEM_TILE_OFF + (size_t)STAGES * STAGE_BYTES;  // 99328
    cudaFuncSetAttribute(gemm_f16_kernel,
                         cudaFuncAttributeMaxDynamicSharedMemorySize, (int)smem_bytes);
    gemm_f16_kernel<<<MT * NT, 128, smem_bytes>>>(bias, out, M, N, K, NT);
}